// round 16
// baseline (speedup 1.0000x reference)
#include <cuda_runtime.h>
#include <math_constants.h>

#define N_TOK 32768   // B*T
#define DIM   128
#define KCB   1024
#define NCB   8

#define MT     64     // tokens per block
#define CCHUNK 128    // codewords per smem chunk
#define TPB    256    // 8 warps: w = tokhalf*4 + cwquarter
#define NQ     4      // cw quarters
#define PAD    136    // padded row stride in words (LDS.64 conflict-free)

__device__ float    g_residual[N_TOK * DIM];
__device__ unsigned g_cb_tf32[NCB * KCB * DIM];   // tf32, PERMUTED within 8-col groups
__device__ float    g_cnorm[NCB * KCB];
__device__ int      g_codes[N_TOK * NCB];
__device__ double   g_loss[NCB];

__device__ __forceinline__ unsigned f2tf32(float f) {
    unsigned u;
    asm("cvt.rna.tf32.f32 %0, %1;" : "=r"(u) : "f"(f));
    return u;
}

__device__ __forceinline__ void mma_tf32(float& d0, float& d1, float& d2, float& d3,
                                         unsigned a0, unsigned a1, unsigned a2, unsigned a3,
                                         unsigned b0, unsigned b1) {
    asm volatile(
        "mma.sync.aligned.m16n8k8.row.col.f32.tf32.tf32.f32 "
        "{%0,%1,%2,%3}, {%4,%5,%6,%7}, {%8,%9}, {%0,%1,%2,%3};"
        : "+f"(d0), "+f"(d1), "+f"(d2), "+f"(d3)
        : "r"(a0), "r"(a1), "r"(a2), "r"(a3), "r"(b0), "r"(b1));
}

// column permutation: cols (c, c+4) of each 8-group become adjacent words
__device__ __host__ __forceinline__ int permc(int c) {
    return (c & ~7) + ((c & 3) << 1) + ((c >> 2) & 1);
}

// full lexicographic (d, k) top-3 insert (merges)
__device__ __forceinline__ void ins3(float* d, int* k, float nd, int nk) {
    if (nd < d[2] || (nd == d[2] && nk < k[2])) {
        d[2] = nd; k[2] = nk;
        if (d[2] < d[1] || (d[2] == d[1] && k[2] < k[1])) {
            float td = d[1]; d[1] = d[2]; d[2] = td;
            int   tk = k[1]; k[1] = k[2]; k[2] = tk;
            if (d[1] < d[0] || (d[1] == d[0] && k[1] < k[0])) {
                td = d[0]; d[0] = d[1]; d[1] = td;
                tk = k[0]; k[0] = k[1]; k[1] = tk;
            }
        }
    }
}

// fast insert: candidates arrive in ascending k within a thread, so strict '<'
// keeps the smallest k on ties (stable) — no int compares needed.
__device__ __forceinline__ void ins3f(float* d, int* k, float nd, int nk) {
    if (nd < d[2]) {
        d[2] = nd; k[2] = nk;
        if (d[2] < d[1]) {
            float td = d[1]; d[1] = d[2]; d[2] = td;
            int   tk = k[1]; k[1] = k[2]; k[2] = tk;
            if (d[1] < d[0]) {
                td = d[0]; d[0] = d[1]; d[1] = td;
                tk = k[0]; k[0] = k[1]; k[1] = tk;
            }
        }
    }
}

__global__ void zero_loss_kernel() {
    if (threadIdx.x < NCB) g_loss[threadIdx.x] = 0.0;
}

__global__ void cnorm_kernel(const float* __restrict__ cbs) {
    int idx = blockIdx.x * blockDim.x + threadIdx.x;
    if (idx >= NCB * KCB) return;
    const float4* v = (const float4*)(cbs + (size_t)idx * DIM);
    float4 a = make_float4(0.f, 0.f, 0.f, 0.f);
#pragma unroll
    for (int i = 0; i < DIM / 4; i++) {
        float4 x = v[i];
        a.x = fmaf(x.x, x.x, a.x);
        a.y = fmaf(x.y, x.y, a.y);
        a.z = fmaf(x.z, x.z, a.z);
        a.w = fmaf(x.w, x.w, a.w);
    }
    g_cnorm[idx] = (a.x + a.y) + (a.z + a.w);
}

__global__ void cvt_cb_kernel(const float* __restrict__ cbs) {
    int i = blockIdx.x * blockDim.x + threadIdx.x;
    if (i >= NCB * KCB * DIM) return;
    int row = i >> 7, c = i & 127;
    g_cb_tf32[((size_t)row << 7) + permc(c)] = f2tf32(cbs[i]);
}

// ------------- Kernel: tf32 MMA distance pass + top-3 + fused exact rescore -------------
__global__ void __launch_bounds__(TPB, 2)
rvq_step(const float* __restrict__ emb,
         const float* __restrict__ cb,   // this codebook fp32 [K, D]
         int cb_idx, int use_emb) {
    extern __shared__ unsigned char smem_raw[];
    unsigned* s_r  = (unsigned*)smem_raw;            // MT*PAD tf32 residual (permuted cols)
    unsigned* s_c  = s_r + MT * PAD;                 // CCHUNK*PAD tf32 codewords (permuted)
    float*    s_cn = (float*)(s_c + CCHUNK * PAD);   // CCHUNK
    float*    s_rn = s_cn + CCHUNK;                  // MT
    float*    s_td = s_rn + MT;                      // NQ*MT*3
    int*      s_tk = (int*)(s_td + NQ * MT * 3);     // NQ*MT*3
    int*      s_fk = s_tk + NQ * MT * 3;             // MT*3 final candidates

    const float*    src = use_emb ? emb : (const float*)g_residual;
    const float*    cn  = g_cnorm + (size_t)cb_idx * KCB;
    const unsigned* cbt = g_cb_tf32 + (size_t)cb_idx * KCB * DIM;

    const int tid  = threadIdx.x;
    const int w    = tid >> 5;       // 0..7
    const int lane = tid & 31;
    const int gid  = lane >> 2;      // 0..7
    const int t4   = lane & 3;       // 0..3
    const int tok0 = blockIdx.x * MT;
    const int tokb = (w >> 2) * 32;  // token half base
    const int cwq  = w & 3;          // cw quarter
    const int cw0w = cwq * 32;

    // ---- fill s_r: tf32, permuted cols; lane q stores uint4 at words [4q,4q+4) ----
    {
        const int q = lane;
        int cols[4];
#pragma unroll
        for (int j = 0; j < 4; j++) {
            int p = 4 * q + j, u = p & 7;
            cols[j] = (p & ~7) + (u >> 1) + ((u & 1) << 2);   // inverse of permc
        }
#pragma unroll
        for (int t = 0; t < MT / 8; t++) {
            int row = w + t * 8;
            const float* srow = src + (size_t)(tok0 + row) * DIM;
            uint4 u4;
            u4.x = f2tf32(srow[cols[0]]);
            u4.y = f2tf32(srow[cols[1]]);
            u4.z = f2tf32(srow[cols[2]]);
            u4.w = f2tf32(srow[cols[3]]);
            *(uint4*)(s_r + row * PAD + 4 * q) = u4;
        }
    }
    // ---- exact rn per token (validated float4-lane tree) ----
    if (tid < MT) {
        const float4* rr = (const float4*)(src + (size_t)(tok0 + tid) * DIM);
        float4 a = make_float4(0.f, 0.f, 0.f, 0.f);
#pragma unroll
        for (int i = 0; i < DIM / 4; i++) {
            float4 x = rr[i];
            a.x = fmaf(x.x, x.x, a.x);
            a.y = fmaf(x.y, x.y, a.y);
            a.z = fmaf(x.z, x.z, a.z);
            a.w = fmaf(x.w, x.w, a.w);
        }
        s_rn[tid] = (a.x + a.y) + (a.z + a.w);
    }
    __syncthreads();

    float rnl[4];
#pragma unroll
    for (int mb = 0; mb < 2; mb++)
#pragma unroll
        for (int h = 0; h < 2; h++)
            rnl[mb * 2 + h] = s_rn[tokb + mb * 16 + gid + h * 8];

    float t3d[4][3];
    int   t3k[4][3];
#pragma unroll
    for (int t = 0; t < 4; t++)
#pragma unroll
        for (int j = 0; j < 3; j++) { t3d[t][j] = CUDART_INF_F; t3k[t][j] = 0x7FFFFFFF; }

    // fragment base pointers: +2*t4 (paired layout), offsets k0 are immediates
    const unsigned* ra0 = s_r + (tokb + gid) * PAD + 2 * t4;
    const unsigned* ra1 = s_r + (tokb + gid + 8) * PAD + 2 * t4;
    const unsigned* rb0 = s_r + (tokb + 16 + gid) * PAD + 2 * t4;
    const unsigned* rb1 = s_r + (tokb + 24 + gid) * PAD + 2 * t4;

#pragma unroll 1
    for (int ch = 0; ch < KCB; ch += CCHUNK) {
        __syncthreads();
        // chunk load: codebook already permuted in global; straight uint4 copy
        {
            const int q = lane;
#pragma unroll
            for (int t = 0; t < CCHUNK / 8; t++) {
                int row = w + t * 8;
                uint4 v = *(const uint4*)(cbt + (size_t)(ch + row) * DIM + 4 * q);
                *(uint4*)(s_c + row * PAD + 4 * q) = v;
            }
        }
        if (tid < CCHUNK) s_cn[tid] = cn[ch + tid];
        __syncthreads();

        float cnl[8];
#pragma unroll
        for (int nb = 0; nb < 4; nb++)
#pragma unroll
            for (int jj = 0; jj < 2; jj++)
                cnl[nb * 2 + jj] = s_cn[cw0w + nb * 8 + 2 * t4 + jj];

        float acc[2][4][4];
#pragma unroll
        for (int mb = 0; mb < 2; mb++)
#pragma unroll
            for (int nb = 0; nb < 4; nb++)
#pragma unroll
                for (int j = 0; j < 4; j++) acc[mb][nb][j] = 0.f;

        const unsigned* cb0 = s_c + (cw0w + 0 * 8 + gid) * PAD + 2 * t4;
        const unsigned* cb1 = s_c + (cw0w + 1 * 8 + gid) * PAD + 2 * t4;
        const unsigned* cb2 = s_c + (cw0w + 2 * 8 + gid) * PAD + 2 * t4;
        const unsigned* cb3 = s_c + (cw0w + 3 * 8 + gid) * PAD + 2 * t4;

#pragma unroll
        for (int k0 = 0; k0 < DIM; k0 += 8) {
            // paired loads: .x = col k0+t4, .y = col k0+4+t4
            uint2 A00 = *(const uint2*)(ra0 + k0);
            uint2 A01 = *(const uint2*)(ra1 + k0);
            uint2 A10 = *(const uint2*)(rb0 + k0);
            uint2 A11 = *(const uint2*)(rb1 + k0);
            uint2 B0  = *(const uint2*)(cb0 + k0);
            uint2 B1  = *(const uint2*)(cb1 + k0);
            uint2 B2  = *(const uint2*)(cb2 + k0);
            uint2 B3  = *(const uint2*)(cb3 + k0);
            mma_tf32(acc[0][0][0], acc[0][0][1], acc[0][0][2], acc[0][0][3],
                     A00.x, A01.x, A00.y, A01.y, B0.x, B0.y);
            mma_tf32(acc[0][1][0], acc[0][1][1], acc[0][1][2], acc[0][1][3],
                     A00.x, A01.x, A00.y, A01.y, B1.x, B1.y);
            mma_tf32(acc[0][2][0], acc[0][2][1], acc[0][2][2], acc[0][2][3],
                     A00.x, A01.x, A00.y, A01.y, B2.x, B2.y);
            mma_tf32(acc[0][3][0], acc[0][3][1], acc[0][3][2], acc[0][3][3],
                     A00.x, A01.x, A00.y, A01.y, B3.x, B3.y);
            mma_tf32(acc[1][0][0], acc[1][0][1], acc[1][0][2], acc[1][0][3],
                     A10.x, A11.x, A10.y, A11.y, B0.x, B0.y);
            mma_tf32(acc[1][1][0], acc[1][1][1], acc[1][1][2], acc[1][1][3],
                     A10.x, A11.x, A10.y, A11.y, B1.x, B1.y);
            mma_tf32(acc[1][2][0], acc[1][2][1], acc[1][2][2], acc[1][2][3],
                     A10.x, A11.x, A10.y, A11.y, B2.x, B2.y);
            mma_tf32(acc[1][3][0], acc[1][3][1], acc[1][3][2], acc[1][3][3],
                     A10.x, A11.x, A10.y, A11.y, B3.x, B3.y);
        }

        // distances -> top-3 (ascending k within thread -> ins3f is exact)
#pragma unroll
        for (int mb = 0; mb < 2; mb++) {
#pragma unroll
            for (int nb = 0; nb < 4; nb++) {
#pragma unroll
                for (int j = 0; j < 4; j++) {
                    int h = j >> 1, jj = j & 1;
                    int ti = mb * 2 + h;
                    int cwl = cw0w + nb * 8 + 2 * t4 + jj;
                    float d = fmaf(-2.f, acc[mb][nb][j], rnl[ti]) + cnl[nb * 2 + jj];
                    ins3f(t3d[ti], t3k[ti], d, ch + cwl);
                }
            }
        }
    }

    // merge top-3 across the 4-lane (t4) group — full lex compare
#pragma unroll
    for (int off = 1; off <= 2; off <<= 1) {
#pragma unroll
        for (int t = 0; t < 4; t++) {
#pragma unroll
            for (int j = 0; j < 3; j++) {
                float od = __shfl_xor_sync(0xFFFFFFFFu, t3d[t][j], off);
                int   ok = __shfl_xor_sync(0xFFFFFFFFu, t3k[t][j], off);
                ins3(t3d[t], t3k[t], od, ok);
            }
        }
    }
    if (t4 == 0) {
#pragma unroll
        for (int mb = 0; mb < 2; mb++) {
#pragma unroll
            for (int h = 0; h < 2; h++) {
                int tok = tokb + mb * 16 + gid + h * 8;
                int ti = mb * 2 + h;
#pragma unroll
                for (int j = 0; j < 3; j++) {
                    s_td[(cwq * MT + tok) * 3 + j] = t3d[ti][j];
                    s_tk[(cwq * MT + tok) * 3 + j] = t3k[ti][j];
                }
            }
        }
    }
    __syncthreads();

    // merge the 4 cw-quarters -> final 3 candidates per token (lex)
    if (tid < MT) {
        float bd[3]; int bk[3];
#pragma unroll
        for (int j = 0; j < 3; j++) { bd[j] = CUDART_INF_F; bk[j] = 0x7FFFFFFF; }
#pragma unroll
        for (int q = 0; q < NQ; q++)
#pragma unroll
            for (int j = 0; j < 3; j++)
                ins3(bd, bk, s_td[(q * MT + tid) * 3 + j], s_tk[(q * MT + tid) * 3 + j]);
#pragma unroll
        for (int j = 0; j < 3; j++) s_fk[tid * 3 + j] = bk[j];
    }
    __syncthreads();

    // ---- fused exact rescore + residual/codes/loss: warp w owns tokens [w*8, w*8+8) ----
    {
        double lsum = 0.0;
#pragma unroll 1
        for (int tt = 0; tt < 8; tt++) {
            int tok = w * 8 + tt;
            int n = tok0 + tok;
            float4 r = *(const float4*)(src + (size_t)n * DIM + lane * 4);
            float rnv = s_rn[tok];
            float bestd = CUDART_INF_F;
            int   bestk = 0x7FFFFFFF;
#pragma unroll 1
            for (int c = 0; c < 3; c++) {
                int k = s_fk[tok * 3 + c];
                float4 cv = *(const float4*)(cb + (size_t)k * DIM + lane * 4);
                float p = fmaf(r.w, cv.w, fmaf(r.z, cv.z, fmaf(r.y, cv.y, r.x * cv.x)));
#pragma unroll
                for (int off = 16; off; off >>= 1)
                    p += __shfl_xor_sync(0xFFFFFFFFu, p, off);
                float d = fmaf(-2.f, p, rnv) + cn[k];
                if (d < bestd || (d == bestd && k < bestk)) { bestd = d; bestk = k; }
            }
            float4 q = *(const float4*)(cb + (size_t)bestk * DIM + lane * 4);
            r.x -= q.x; r.y -= q.y; r.z -= q.z; r.w -= q.w;
            *(float4*)(g_residual + (size_t)n * DIM + lane * 4) = r;
            lsum += (double)r.x * (double)r.x + (double)r.y * (double)r.y
                  + (double)r.z * (double)r.z + (double)r.w * (double)r.w;
            if (lane == 0) g_codes[n * NCB + cb_idx] = bestk;
        }
#pragma unroll
        for (int off = 16; off; off >>= 1)
            lsum += __shfl_down_sync(0xFFFFFFFFu, lsum, off);
        if (lane == 0) atomicAdd(&g_loss[cb_idx], lsum);
    }
}

__global__ void finalize_kernel(const float* __restrict__ emb,
                                const float* __restrict__ cbs,
                                float* oc, float* oq, float* ol) {
    int n = blockIdx.x * blockDim.x + threadIdx.x;
    if (n >= N_TOK) return;

    float4 q[DIM / 4];
#pragma unroll
    for (int i = 0; i < DIM / 4; i++) q[i] = make_float4(0.f, 0.f, 0.f, 0.f);

#pragma unroll 1
    for (int c = 0; c < NCB; c++) {
        int k = g_codes[n * NCB + c];
        const float4* w = (const float4*)(cbs + ((size_t)c * KCB + k) * DIM);
#pragma unroll
        for (int i = 0; i < DIM / 4; i++) {
            float4 x = w[i];
            q[i].x += x.x; q[i].y += x.y; q[i].z += x.z; q[i].w += x.w;
        }
        if (oc) oc[n * NCB + c] = (float)k;
    }

    if (oq) {
        const float4* ev = (const float4*)(emb + (size_t)n * DIM);
        float4* ov = (float4*)(oq + (size_t)n * DIM);
#pragma unroll
        for (int i = 0; i < DIM / 4; i++) {
            float4 e = ev[i];
            float4 o;
            o.x = e.x + (q[i].x - e.x);
            o.y = e.y + (q[i].y - e.y);
            o.z = e.z + (q[i].z - e.z);
            o.w = e.w + (q[i].w - e.w);
            ov[i] = o;
        }
    }

    if (n == 0 && ol) {
        float l = 0.f;
#pragma unroll 1
        for (int c = 0; c < NCB; c++)
            l = l + (float)(g_loss[c] / (double)((size_t)N_TOK * DIM));
        *ol = l / (float)NCB;
    }
}

extern "C" void kernel_launch(void* const* d_in, const int* in_sizes, int n_in,
                              void* d_out, int out_size) {
    const float* emb = (const float*)d_in[0];  // [8,4096,128] f32
    const float* cbs = (const float*)d_in[1];  // [8,1024,128] f32
    float* out = (float*)d_out;

    const long CODES_ELEMS = (long)N_TOK * NCB;
    const long QUANT_ELEMS = (long)N_TOK * DIM;
    const long TOTAL = CODES_ELEMS + QUANT_ELEMS + 1;

    float *oc = nullptr, *oq = nullptr, *ol = nullptr;
    if ((long)out_size == TOTAL) {
        oc = out; oq = out + CODES_ELEMS; ol = out + CODES_ELEMS + QUANT_ELEMS;
    } else if ((long)out_size == QUANT_ELEMS) {
        oq = out;
    } else if ((long)out_size == CODES_ELEMS) {
        oc = out;
    } else if (out_size == 1) {
        ol = out;
    } else {
        oc = out;
        if ((long)out_size >= CODES_ELEMS + QUANT_ELEMS) oq = out + CODES_ELEMS;
        if ((long)out_size >= TOTAL) ol = out + CODES_ELEMS + QUANT_ELEMS;
    }

    const int SMEM_BYTES = (MT * PAD + CCHUNK * PAD) * 4   // padded/permuted tf32 tiles
                         + CCHUNK * 4 + MT * 4             // cn, rn
                         + NQ * MT * 3 * 4 * 2             // per-quarter top-3 d/k
                         + MT * 3 * 4;                     // final candidates
    cudaFuncSetAttribute(rvq_step,
                         cudaFuncAttributeMaxDynamicSharedMemorySize, SMEM_BYTES);

    zero_loss_kernel<<<1, 32>>>();
    cnorm_kernel<<<(NCB * KCB + 127) / 128, 128>>>(cbs);
    cvt_cb_kernel<<<(NCB * KCB * DIM + 255) / 256, 256>>>(cbs);

    for (int c = 0; c < NCB; c++) {
        const float* cb = cbs + (size_t)c * KCB * DIM;
        rvq_step<<<N_TOK / MT, TPB, SMEM_BYTES>>>(emb, cb, c, c == 0 ? 1 : 0);
    }

    finalize_kernel<<<(N_TOK + 127) / 128, 128>>>(emb, cbs, oc, oq, ol);
}

// round 17
// speedup vs baseline: 1.4273x; 1.4273x over previous
#include <cuda_runtime.h>
#include <math_constants.h>

#define N_TOK 32768   // B*T
#define DIM   128
#define KCB   1024
#define NCB   8

#define MT     128    // tokens per block (4 quarters x 32)
#define CCHUNK 128    // codewords per chunk (4 quarters x 32)
#define NCHUNK (KCB / CCHUNK)
#define TPB    512    // 16 warps: w = tokq*4 + cwq
#define NQ     4      // cw quarters
#define PAD    132    // padded row stride in words (affine, conflict-free)
#define CSZ    (CCHUNK * PAD)   // one codeword buffer in words

__device__ float    g_residual[N_TOK * DIM];
__device__ unsigned g_cb_tf32[NCB * KCB * DIM];
__device__ float    g_cnorm[NCB * KCB];
__device__ float    g_rn[N_TOK];
__device__ int      g_topk[N_TOK * 3];
__device__ int      g_codes[N_TOK * NCB];
__device__ double   g_loss[NCB];

__device__ __forceinline__ unsigned f2tf32(float f) {
    unsigned u;
    asm("cvt.rna.tf32.f32 %0, %1;" : "=r"(u) : "f"(f));
    return u;
}

__device__ __forceinline__ void mma_tf32(float& d0, float& d1, float& d2, float& d3,
                                         unsigned a0, unsigned a1, unsigned a2, unsigned a3,
                                         unsigned b0, unsigned b1) {
    asm volatile(
        "mma.sync.aligned.m16n8k8.row.col.f32.tf32.tf32.f32 "
        "{%0,%1,%2,%3}, {%4,%5,%6,%7}, {%8,%9}, {%0,%1,%2,%3};"
        : "+f"(d0), "+f"(d1), "+f"(d2), "+f"(d3)
        : "r"(a0), "r"(a1), "r"(a2), "r"(a3), "r"(b0), "r"(b1));
}

__device__ __forceinline__ void cp_async16(void* smem_dst, const void* gmem_src) {
    unsigned dst;
    asm("{ .reg .u64 t; cvta.to.shared.u64 t, %1; cvt.u32.u64 %0, t; }"
        : "=r"(dst) : "l"(smem_dst));
    asm volatile("cp.async.cg.shared.global [%0], [%1], 16;"
                 :: "r"(dst), "l"(gmem_src) : "memory");
}
__device__ __forceinline__ void cp_async_commit() {
    asm volatile("cp.async.commit_group;" ::: "memory");
}
__device__ __forceinline__ void cp_async_wait_all() {
    asm volatile("cp.async.wait_group 0;" ::: "memory");
}

// full lexicographic (d, k) top-3 insert (merges)
__device__ __forceinline__ void ins3(float* d, int* k, float nd, int nk) {
    if (nd < d[2] || (nd == d[2] && nk < k[2])) {
        d[2] = nd; k[2] = nk;
        if (d[2] < d[1] || (d[2] == d[1] && k[2] < k[1])) {
            float td = d[1]; d[1] = d[2]; d[2] = td;
            int   tk = k[1]; k[1] = k[2]; k[2] = tk;
            if (d[1] < d[0] || (d[1] == d[0] && k[1] < k[0])) {
                td = d[0]; d[0] = d[1]; d[1] = td;
                tk = k[0]; k[0] = k[1]; k[1] = tk;
            }
        }
    }
}

// fast insert: per-token candidates arrive in ascending k within a thread,
// so strict '<' keeps smallest k on ties (validated rel_err 0.0 in R16).
__device__ __forceinline__ void ins3f(float* d, int* k, float nd, int nk) {
    if (nd < d[2]) {
        d[2] = nd; k[2] = nk;
        if (d[2] < d[1]) {
            float td = d[1]; d[1] = d[2]; d[2] = td;
            int   tk = k[1]; k[1] = k[2]; k[2] = tk;
            if (d[1] < d[0]) {
                td = d[0]; d[0] = d[1]; d[1] = td;
                tk = k[0]; k[0] = k[1]; k[1] = tk;
            }
        }
    }
}

__global__ void zero_loss_kernel() {
    if (threadIdx.x < NCB) g_loss[threadIdx.x] = 0.0;
}

__global__ void cnorm_kernel(const float* __restrict__ cbs) {
    int idx = blockIdx.x * blockDim.x + threadIdx.x;
    if (idx >= NCB * KCB) return;
    const float4* v = (const float4*)(cbs + (size_t)idx * DIM);
    float4 a = make_float4(0.f, 0.f, 0.f, 0.f);
#pragma unroll
    for (int i = 0; i < DIM / 4; i++) {
        float4 x = v[i];
        a.x = fmaf(x.x, x.x, a.x);
        a.y = fmaf(x.y, x.y, a.y);
        a.z = fmaf(x.z, x.z, a.z);
        a.w = fmaf(x.w, x.w, a.w);
    }
    g_cnorm[idx] = (a.x + a.y) + (a.z + a.w);
}

__global__ void cvt_cb_kernel(const float* __restrict__ cbs) {
    int i = blockIdx.x * blockDim.x + threadIdx.x;
    if (i < NCB * KCB * DIM) g_cb_tf32[i] = f2tf32(cbs[i]);
}

// ------ Kernel A: tf32 MMA distance pass (cp.async double-buffered) -> top-3 ------
__global__ void __launch_bounds__(TPB, 1)
rvq_dist_mma(const float* __restrict__ emb, int cb_idx, int use_emb) {
    extern __shared__ unsigned char smem_raw[];
    unsigned* s_r  = (unsigned*)smem_raw;            // MT*PAD tf32 residual
    unsigned* s_c  = s_r + MT * PAD;                 // 2 * CSZ ping-pong codewords
    float*    s_rn = (float*)(s_c + 2 * CSZ);        // MT
    float*    s_td = s_rn + MT;                      // NQ*MT*3
    int*      s_tk = (int*)(s_td + NQ * MT * 3);     // NQ*MT*3

    const float*    src = use_emb ? emb : (const float*)g_residual;
    const float*    cn  = g_cnorm + (size_t)cb_idx * KCB;
    const unsigned* cbt = g_cb_tf32 + (size_t)cb_idx * KCB * DIM;

    const int tid  = threadIdx.x;
    const int w    = tid >> 5;       // 0..15
    const int lane = tid & 31;
    const int gid  = lane >> 2;      // 0..7
    const int t4   = lane & 3;       // 0..3
    const int tok0 = blockIdx.x * MT;
    const int tokb = (w >> 2) * 32;  // token quarter base
    const int cwq  = w & 3;          // cw quarter
    const int cw0w = cwq * 32;

    // ---- prefetch chunk 0 into buffer 0 (overlaps the s_r fill below) ----
    {
#pragma unroll
        for (int s = 0; s < (CCHUNK * 32) / TPB; s++) {
            int idx = tid + s * TPB;
            int row = idx >> 5, q = idx & 31;
            cp_async16(s_c + row * PAD + 4 * q, cbt + (size_t)row * DIM + 4 * q);
        }
        cp_async_commit();
    }

    // ---- fill s_r (tf32, padded rows): warp w handles rows w + t*16 ----
    {
        const int q = lane;
#pragma unroll
        for (int t = 0; t < MT / 16; t++) {
            int row = w + t * 16;
            float4 v = *(const float4*)(src + (size_t)(tok0 + row) * DIM + q * 4);
            uint4 u;
            u.x = f2tf32(v.x); u.y = f2tf32(v.y);
            u.z = f2tf32(v.z); u.w = f2tf32(v.w);
            *(uint4*)(s_r + row * PAD + q * 4) = u;
        }
    }
    // ---- exact rn per token (validated float4-lane tree); persist ----
    if (tid < MT) {
        const float4* rr = (const float4*)(src + (size_t)(tok0 + tid) * DIM);
        float4 a = make_float4(0.f, 0.f, 0.f, 0.f);
#pragma unroll
        for (int i = 0; i < DIM / 4; i++) {
            float4 x = rr[i];
            a.x = fmaf(x.x, x.x, a.x);
            a.y = fmaf(x.y, x.y, a.y);
            a.z = fmaf(x.z, x.z, a.z);
            a.w = fmaf(x.w, x.w, a.w);
        }
        float rn = (a.x + a.y) + (a.z + a.w);
        s_rn[tid] = rn;
        g_rn[tok0 + tid] = rn;
    }

    float t3d[4][3];
    int   t3k[4][3];
#pragma unroll
    for (int t = 0; t < 4; t++)
#pragma unroll
        for (int j = 0; j < 3; j++) { t3d[t][j] = CUDART_INF_F; t3k[t][j] = 0x7FFFFFFF; }

    // fragment base pointers into s_r (offsets become immediates under unroll)
    const unsigned* ra0 = s_r + (tokb + gid) * PAD + t4;
    const unsigned* ra1 = s_r + (tokb + gid + 8) * PAD + t4;
    const unsigned* rb0 = s_r + (tokb + 16 + gid) * PAD + t4;
    const unsigned* rb1 = s_r + (tokb + 24 + gid) * PAD + t4;

    float rnl[4];

#pragma unroll 1
    for (int ci = 0; ci < NCHUNK; ci++) {
        const int ch = ci * CCHUNK;
        cp_async_wait_all();     // chunk ci landed in buffer ci&1
        __syncthreads();         // visible to all; all done reading buffer (ci+1)&1

        if (ci == 0) {
            // rnl depends on s_rn (filled pre-loop, published by this barrier)
#pragma unroll
            for (int mb = 0; mb < 2; mb++)
#pragma unroll
                for (int h = 0; h < 2; h++)
                    rnl[mb * 2 + h] = s_rn[tokb + mb * 16 + gid + h * 8];
        }

        // prefetch next chunk into the other buffer
        if (ci + 1 < NCHUNK) {
            unsigned* dst = s_c + ((ci + 1) & 1) * CSZ;
            const unsigned* gsrc = cbt + (size_t)(ch + CCHUNK) * DIM;
#pragma unroll
            for (int s = 0; s < (CCHUNK * 32) / TPB; s++) {
                int idx = tid + s * TPB;
                int row = idx >> 5, q = idx & 31;
                cp_async16(dst + row * PAD + 4 * q, gsrc + (size_t)row * DIM + 4 * q);
            }
            cp_async_commit();
        } else {
            cp_async_commit();   // empty group so wait_group 0 stays cheap/legal
        }

        const unsigned* buf = s_c + (ci & 1) * CSZ;

        // per-thread codeword norms for this chunk (L1-resident 4KB table)
        float cnl[8];
#pragma unroll
        for (int nb = 0; nb < 4; nb++)
#pragma unroll
            for (int jj = 0; jj < 2; jj++)
                cnl[nb * 2 + jj] = __ldg(&cn[ch + cw0w + nb * 8 + 2 * t4 + jj]);

        float acc[2][4][4];
#pragma unroll
        for (int mb = 0; mb < 2; mb++)
#pragma unroll
            for (int nb = 0; nb < 4; nb++)
#pragma unroll
                for (int j = 0; j < 4; j++) acc[mb][nb][j] = 0.f;

        const unsigned* cb0 = buf + (cw0w + 0 * 8 + gid) * PAD + t4;
        const unsigned* cb1 = buf + (cw0w + 1 * 8 + gid) * PAD + t4;
        const unsigned* cb2 = buf + (cw0w + 2 * 8 + gid) * PAD + t4;
        const unsigned* cb3 = buf + (cw0w + 3 * 8 + gid) * PAD + t4;

#pragma unroll
        for (int k0 = 0; k0 < DIM; k0 += 8) {
            unsigned a[2][4], b[4][2];
            a[0][0] = ra0[k0];     a[0][1] = ra1[k0];
            a[0][2] = ra0[k0 + 4]; a[0][3] = ra1[k0 + 4];
            a[1][0] = rb0[k0];     a[1][1] = rb1[k0];
            a[1][2] = rb0[k0 + 4]; a[1][3] = rb1[k0 + 4];
            b[0][0] = cb0[k0];     b[0][1] = cb0[k0 + 4];
            b[1][0] = cb1[k0];     b[1][1] = cb1[k0 + 4];
            b[2][0] = cb2[k0];     b[2][1] = cb2[k0 + 4];
            b[3][0] = cb3[k0];     b[3][1] = cb3[k0 + 4];
#pragma unroll
            for (int mb = 0; mb < 2; mb++)
#pragma unroll
                for (int nb = 0; nb < 4; nb++)
                    mma_tf32(acc[mb][nb][0], acc[mb][nb][1], acc[mb][nb][2], acc[mb][nb][3],
                             a[mb][0], a[mb][1], a[mb][2], a[mb][3],
                             b[nb][0], b[nb][1]);
        }

        // distances -> top-3 (ascending k per token within thread -> ins3f exact)
#pragma unroll
        for (int mb = 0; mb < 2; mb++) {
#pragma unroll
            for (int nb = 0; nb < 4; nb++) {
#pragma unroll
                for (int j = 0; j < 4; j++) {
                    int h = j >> 1, jj = j & 1;
                    int ti = mb * 2 + h;
                    int cwl = cw0w + nb * 8 + 2 * t4 + jj;
                    float d = fmaf(-2.f, acc[mb][nb][j], rnl[ti]) + cnl[nb * 2 + jj];
                    ins3f(t3d[ti], t3k[ti], d, ch + cwl);
                }
            }
        }
    }

    // merge top-3 across the 4-lane (t4) group — full lex compare
#pragma unroll
    for (int off = 1; off <= 2; off <<= 1) {
#pragma unroll
        for (int t = 0; t < 4; t++) {
#pragma unroll
            for (int j = 0; j < 3; j++) {
                float od = __shfl_xor_sync(0xFFFFFFFFu, t3d[t][j], off);
                int   ok = __shfl_xor_sync(0xFFFFFFFFu, t3k[t][j], off);
                ins3(t3d[t], t3k[t], od, ok);
            }
        }
    }
    if (t4 == 0) {
#pragma unroll
        for (int mb = 0; mb < 2; mb++) {
#pragma unroll
            for (int h = 0; h < 2; h++) {
                int tok = tokb + mb * 16 + gid + h * 8;
                int ti = mb * 2 + h;
#pragma unroll
                for (int j = 0; j < 3; j++) {
                    s_td[(cwq * MT + tok) * 3 + j] = t3d[ti][j];
                    s_tk[(cwq * MT + tok) * 3 + j] = t3k[ti][j];
                }
            }
        }
    }
    __syncthreads();

    // merge the 4 cw-quarters, write top-3 k's per token
    if (tid < MT) {
        float bd[3]; int bk[3];
#pragma unroll
        for (int j = 0; j < 3; j++) { bd[j] = CUDART_INF_F; bk[j] = 0x7FFFFFFF; }
#pragma unroll
        for (int q = 0; q < NQ; q++)
#pragma unroll
            for (int j = 0; j < 3; j++)
                ins3(bd, bk, s_td[(q * MT + tid) * 3 + j], s_tk[(q * MT + tid) * 3 + j]);
#pragma unroll
        for (int j = 0; j < 3; j++) g_topk[(tok0 + tid) * 3 + j] = bk[j];
    }
}

// ---------------- Kernel B: exact fp32 rescore + residual/codes/loss ----------------
__global__ void __launch_bounds__(128)
rvq_rescore(const float* __restrict__ emb,
            const float* __restrict__ cb,   // this codebook fp32 [K, D]
            int cb_idx, int use_emb) {
    const float* src = use_emb ? emb : (const float*)g_residual;
    const float* cn  = g_cnorm + (size_t)cb_idx * KCB;
    const int n = blockIdx.x * 128 + threadIdx.x;

    float rnv = g_rn[n];
    int bk[3];
#pragma unroll
    for (int j = 0; j < 3; j++) bk[j] = g_topk[n * 3 + j];

    float4 r[DIM / 4];
    const float4* rr = (const float4*)(src + (size_t)n * DIM);
#pragma unroll
    for (int i = 0; i < DIM / 4; i++) r[i] = rr[i];

    float bestd = CUDART_INF_F;
    int   bestk = 0x7FFFFFFF;
#pragma unroll 1
    for (int c = 0; c < 3; c++) {
        int k = bk[c];
        const float4* cv = (const float4*)(cb + (size_t)k * DIM);
        float4 a = make_float4(0.f, 0.f, 0.f, 0.f);
#pragma unroll
        for (int i = 0; i < DIM / 4; i++) {
            float4 x = cv[i];
            a.x = fmaf(r[i].x, x.x, a.x);
            a.y = fmaf(r[i].y, x.y, a.y);
            a.z = fmaf(r[i].z, x.z, a.z);
            a.w = fmaf(r[i].w, x.w, a.w);
        }
        float dot = (a.x + a.y) + (a.z + a.w);
        float d = fmaf(-2.f, dot, rnv) + cn[k];
        if (d < bestd || (d == bestd && k < bestk)) { bestd = d; bestk = k; }
    }

    double lsum = 0.0;
    const float4* qv = (const float4*)(cb + (size_t)bestk * DIM);
    float4* rv = (float4*)(g_residual + (size_t)n * DIM);
#pragma unroll
    for (int i = 0; i < DIM / 4; i++) {
        float4 rr2 = r[i];
        float4 q = qv[i];
        rr2.x -= q.x; rr2.y -= q.y; rr2.z -= q.z; rr2.w -= q.w;
        lsum += (double)rr2.x * (double)rr2.x;
        lsum += (double)rr2.y * (double)rr2.y;
        lsum += (double)rr2.z * (double)rr2.z;
        lsum += (double)rr2.w * (double)rr2.w;
        rv[i] = rr2;
    }
    g_codes[n * NCB + cb_idx] = bestk;

#pragma unroll
    for (int off = 16; off; off >>= 1)
        lsum += __shfl_down_sync(0xFFFFFFFFu, lsum, off);
    if ((threadIdx.x & 31) == 0) atomicAdd(&g_loss[cb_idx], lsum);
}

__global__ void finalize_kernel(const float* __restrict__ emb,
                                const float* __restrict__ cbs,
                                float* oc, float* oq, float* ol) {
    int n = blockIdx.x * blockDim.x + threadIdx.x;
    if (n >= N_TOK) return;

    float4 q[DIM / 4];
#pragma unroll
    for (int i = 0; i < DIM / 4; i++) q[i] = make_float4(0.f, 0.f, 0.f, 0.f);

#pragma unroll 1
    for (int c = 0; c < NCB; c++) {
        int k = g_codes[n * NCB + c];
        const float4* w = (const float4*)(cbs + ((size_t)c * KCB + k) * DIM);
#pragma unroll
        for (int i = 0; i < DIM / 4; i++) {
            float4 x = w[i];
            q[i].x += x.x; q[i].y += x.y; q[i].z += x.z; q[i].w += x.w;
        }
        if (oc) oc[n * NCB + c] = (float)k;
    }

    if (oq) {
        const float4* ev = (const float4*)(emb + (size_t)n * DIM);
        float4* ov = (float4*)(oq + (size_t)n * DIM);
#pragma unroll
        for (int i = 0; i < DIM / 4; i++) {
            float4 e = ev[i];
            float4 o;
            o.x = e.x + (q[i].x - e.x);
            o.y = e.y + (q[i].y - e.y);
            o.z = e.z + (q[i].z - e.z);
            o.w = e.w + (q[i].w - e.w);
            ov[i] = o;
        }
    }

    if (n == 0 && ol) {
        float l = 0.f;
#pragma unroll 1
        for (int c = 0; c < NCB; c++)
            l = l + (float)(g_loss[c] / (double)((size_t)N_TOK * DIM));
        *ol = l / (float)NCB;
    }
}

extern "C" void kernel_launch(void* const* d_in, const int* in_sizes, int n_in,
                              void* d_out, int out_size) {
    const float* emb = (const float*)d_in[0];  // [8,4096,128] f32
    const float* cbs = (const float*)d_in[1];  // [8,1024,128] f32
    float* out = (float*)d_out;

    const long CODES_ELEMS = (long)N_TOK * NCB;
    const long QUANT_ELEMS = (long)N_TOK * DIM;
    const long TOTAL = CODES_ELEMS + QUANT_ELEMS + 1;

    float *oc = nullptr, *oq = nullptr, *ol = nullptr;
    if ((long)out_size == TOTAL) {
        oc = out; oq = out + CODES_ELEMS; ol = out + CODES_ELEMS + QUANT_ELEMS;
    } else if ((long)out_size == QUANT_ELEMS) {
        oq = out;
    } else if ((long)out_size == CODES_ELEMS) {
        oc = out;
    } else if (out_size == 1) {
        ol = out;
    } else {
        oc = out;
        if ((long)out_size >= CODES_ELEMS + QUANT_ELEMS) oq = out + CODES_ELEMS;
        if ((long)out_size >= TOTAL) ol = out + CODES_ELEMS + QUANT_ELEMS;
    }

    const int SMEM_BYTES = (MT * PAD + 2 * CSZ) * 4    // s_r + ping-pong s_c
                         + MT * 4                      // rn
                         + NQ * MT * 3 * 4 * 2;        // per-quarter top-3 d/k
    cudaFuncSetAttribute(rvq_dist_mma,
                         cudaFuncAttributeMaxDynamicSharedMemorySize, SMEM_BYTES);

    zero_loss_kernel<<<1, 32>>>();
    cnorm_kernel<<<(NCB * KCB + 127) / 128, 128>>>(cbs);
    cvt_cb_kernel<<<(NCB * KCB * DIM + 255) / 256, 256>>>(cbs);

    for (int c = 0; c < NCB; c++) {
        const float* cb = cbs + (size_t)c * KCB * DIM;
        rvq_dist_mma<<<N_TOK / MT, TPB, SMEM_BYTES>>>(emb, c, c == 0 ? 1 : 0);
        rvq_rescore<<<N_TOK / 128, 128>>>(emb, cb, c, c == 0 ? 1 : 0);
    }

    finalize_kernel<<<(N_TOK + 127) / 128, 128>>>(emb, cbs, oc, oq, ol);
}